// round 2
// baseline (speedup 1.0000x reference)
#include <cuda_runtime.h>

#define NNODES_MAX 50000
#define HF 128

// Scratch: U[n][j] = sum_k W1[j][k]*h[n][k],  V[n][j] = sum_k W1[j][128+k]*h[n][k]
__device__ float g_U[NNODES_MAX * HF];
__device__ float g_V[NNODES_MAX * HF];
__device__ int   g_idx_is64;   // 1 if src/dst are int64, 0 if int32

// ---------------------------------------------------------------------------
// Kernel 0: detect index dtype. If the buffer really holds int64 indices in
// [0, 50000), every high 32-bit word is zero. If it holds int32 indices, the
// "high words" are random node ids (OR over 2048 of them is ~never zero).
// ---------------------------------------------------------------------------
__global__ void detect_idx_dtype_kernel(const unsigned int* __restrict__ src_raw,
                                        int n_edges)
{
    __shared__ unsigned int red[256];
    int tid = threadIdx.x;
    // Look at high words of the first min(2048, n_edges/2) 8-byte slots.
    int slots = n_edges >> 1;
    if (slots > 2048) slots = 2048;
    unsigned int acc = 0;
    for (int i = tid; i < slots; i += 256)
        acc |= src_raw[2 * i + 1];
    red[tid] = acc;
    __syncthreads();
    for (int s = 128; s; s >>= 1) {
        if (tid < s) red[tid] |= red[tid + s];
        __syncthreads();
    }
    if (tid == 0) g_idx_is64 = (red[0] == 0u) ? 1 : 0;
}

// ---------------------------------------------------------------------------
// Kernel 1: node GEMM  C[n][c] = sum_k h[n][k] * Wc[k][c]   (M=n_nodes, N=256, K=128)
//   Wc[k][c] = W1[c & 127][ ((c>>7)<<7) + k ]
// CTA tile: 64 nodes x 256 cols, K chunked by 32. Thread tile 8x8.
// ---------------------------------------------------------------------------
__global__ __launch_bounds__(256) void node_gemm_kernel(
    const float* __restrict__ h,
    const float* __restrict__ W1,
    int n_nodes)
{
    __shared__ float Hs[64][32];    // 8 KB
    __shared__ float Ws[32][257];   // ~32.9 KB (pad -> conflict-free)

    const int tid = threadIdx.x;
    const int tx  = tid & 31;       // col group
    const int ty  = tid >> 5;       // node group (0..7)
    const int n0  = blockIdx.x * 64;

    float acc[8][8];
#pragma unroll
    for (int i = 0; i < 8; i++)
#pragma unroll
        for (int j = 0; j < 8; j++) acc[i][j] = 0.f;

    for (int kc = 0; kc < 4; kc++) {
        __syncthreads();
        // H chunk: 64 rows x 32 cols as float4
#pragma unroll
        for (int e = tid; e < 64 * 8; e += 256) {
            int r  = e >> 3;
            int c4 = e & 7;
            int n  = n0 + r;
            float4 v = make_float4(0.f, 0.f, 0.f, 0.f);
            if (n < n_nodes)
                v = *(const float4*)(h + (size_t)n * HF + kc * 32 + c4 * 4);
            *(float4*)&Hs[r][c4 * 4] = v;
        }
        // W chunk: Ws[k][c]
#pragma unroll
        for (int e = tid; e < 2048; e += 256) {
            int c   = e >> 3;                 // 0..255
            int k0  = (e & 7) * 4;            // 0,4,...,28
            int row = c & 127;
            int gk  = ((c >> 7) << 7) + kc * 32 + k0;
            float4 w = *(const float4*)(W1 + row * 256 + gk);
            Ws[k0 + 0][c] = w.x;
            Ws[k0 + 1][c] = w.y;
            Ws[k0 + 2][c] = w.z;
            Ws[k0 + 3][c] = w.w;
        }
        __syncthreads();

#pragma unroll
        for (int k = 0; k < 32; k++) {
            float a[8], b[8];
#pragma unroll
            for (int i = 0; i < 8; i++) a[i] = Hs[ty + 8 * i][k];   // broadcast
#pragma unroll
            for (int j = 0; j < 8; j++) b[j] = Ws[k][tx + 32 * j];  // conflict-free
#pragma unroll
            for (int i = 0; i < 8; i++)
#pragma unroll
                for (int j = 0; j < 8; j++)
                    acc[i][j] = fmaf(a[i], b[j], acc[i][j]);
        }
    }

#pragma unroll
    for (int i = 0; i < 8; i++) {
        int n = n0 + ty + 8 * i;
        if (n < n_nodes) {
            float* __restrict__ urow = g_U + (size_t)n * HF;
            float* __restrict__ vrow = g_V + (size_t)n * HF;
#pragma unroll
            for (int j = 0; j < 8; j++) {
                int c = tx + 32 * j;
                if (c < 128) urow[c] = acc[i][j];
                else         vrow[c - 128] = acc[i][j];
            }
        }
    }
}

// ---------------------------------------------------------------------------
// Kernel 2: per-edge  score = W2 . relu(U[src] + V[dst] + b1) + b2
// One warp per edge, lane handles 4 consecutive features via float4.
// Index dtype resolved at runtime via g_idx_is64.
// ---------------------------------------------------------------------------
__global__ __launch_bounds__(256) void edge_score_kernel(
    const void* __restrict__ src_raw,
    const void* __restrict__ dst_raw,
    const float* __restrict__ b1,
    const float* __restrict__ W2,
    const float* __restrict__ b2,
    float* __restrict__ out,
    int n_edges,
    int n_nodes)
{
    const int lane   = threadIdx.x & 31;
    const int warp   = (blockIdx.x * blockDim.x + threadIdx.x) >> 5;
    const int nwarps = (gridDim.x * blockDim.x) >> 5;

    const float4 b14 = ((const float4*)b1)[lane];
    const float4 w24 = ((const float4*)W2)[lane];
    const float  b2v = __ldg(b2);
    const int    is64 = g_idx_is64;

    const int*       src32 = (const int*)src_raw;
    const int*       dst32 = (const int*)dst_raw;
    const long long* src64 = (const long long*)src_raw;
    const long long* dst64 = (const long long*)dst_raw;

    for (int e = warp; e < n_edges; e += nwarps) {
        int s, d;
        if (is64) {
            s = (int)__ldg(src64 + e);
            d = (int)__ldg(dst64 + e);
        } else {
            s = __ldg(src32 + e);
            d = __ldg(dst32 + e);
        }
        // Safety clamp: a bad index can only give a wrong value, never a fault.
        unsigned int su = ((unsigned int)s < (unsigned int)n_nodes) ? (unsigned int)s : 0u;
        unsigned int du = ((unsigned int)d < (unsigned int)n_nodes) ? (unsigned int)d : 0u;

        float4 u = *(const float4*)(g_U + (size_t)su * HF + lane * 4);
        float4 v = *(const float4*)(g_V + (size_t)du * HF + lane * 4);

        float acc = fmaxf(u.x + v.x + b14.x, 0.f) * w24.x;
        acc = fmaf(fmaxf(u.y + v.y + b14.y, 0.f), w24.y, acc);
        acc = fmaf(fmaxf(u.z + v.z + b14.z, 0.f), w24.z, acc);
        acc = fmaf(fmaxf(u.w + v.w + b14.w, 0.f), w24.w, acc);

#pragma unroll
        for (int o = 16; o; o >>= 1)
            acc += __shfl_xor_sync(0xffffffffu, acc, o);

        if (lane == 0) out[e] = acc + b2v;
    }
}

// ---------------------------------------------------------------------------
// Launch
// ---------------------------------------------------------------------------
extern "C" void kernel_launch(void* const* d_in, const int* in_sizes, int n_in,
                              void* d_out, int out_size)
{
    const float* h   = (const float*)d_in[0];
    const void*  src = d_in[1];
    const void*  dst = d_in[2];
    const float* W1  = (const float*)d_in[3];
    const float* b1  = (const float*)d_in[4];
    const float* W2  = (const float*)d_in[5];
    const float* b2  = (const float*)d_in[6];
    float* out = (float*)d_out;

    const int n_nodes = in_sizes[0] / HF;
    const int n_edges = in_sizes[1];

    detect_idx_dtype_kernel<<<1, 256>>>((const unsigned int*)src, n_edges);
    node_gemm_kernel<<<(n_nodes + 63) / 64, 256>>>(h, W1, n_nodes);
    edge_score_kernel<<<1184, 256>>>(src, dst, b1, W2, b2, out, n_edges, n_nodes);
}

// round 3
// speedup vs baseline: 1.1372x; 1.1372x over previous
#include <cuda_runtime.h>

#define NNODES_MAX 50000
#define HF 128

// Scratch: U[n][j] = sum_k W1[j][k]*h[n][k],  V[n][j] = sum_k W1[j][128+k]*h[n][k]
__device__ float g_U[NNODES_MAX * HF];
__device__ float g_V[NNODES_MAX * HF];

// ---------------------------------------------------------------------------
// Kernel 1: node GEMM  C[n][c] = sum_k h[n][k] * Wc[k][c]   (M=n_nodes, N=256, K=128)
//   Wc[k][c] = W1[c & 127][ ((c>>7)<<7) + k ]
// CTA tile: 64 nodes x 256 cols, K chunked by 32. Thread tile: 8 rows x 4 col-PAIRS,
// accumulated with packed fma.rn.f32x2 (2 fp32 FMAs per instruction).
// ---------------------------------------------------------------------------
__global__ __launch_bounds__(256, 2) void node_gemm_kernel(
    const float* __restrict__ h,
    const float* __restrict__ W1,
    int n_nodes)
{
    __shared__ float Hs[64][32];     // 8 KB
    __shared__ float Ws[32][258];    // 33 KB, even pad -> 8B-aligned rows, conflict-free

    const int tid = threadIdx.x;
    const int tx  = tid & 31;        // lane: owns col pairs (2*tx + 64*j, +1)
    const int ty  = tid >> 5;        // warp: owns rows ty + 8*i
    const int n0  = blockIdx.x * 64;

    unsigned long long acc2[8][4];   // (row i, col-pair j), each = 2 packed floats
#pragma unroll
    for (int i = 0; i < 8; i++)
#pragma unroll
        for (int j = 0; j < 4; j++) acc2[i][j] = 0ull;

    for (int kc = 0; kc < 4; kc++) {
        __syncthreads();
        // H chunk: 64 rows x 32 cols as float4
#pragma unroll
        for (int e = tid; e < 64 * 8; e += 256) {
            int r  = e >> 3;
            int c4 = e & 7;
            int n  = n0 + r;
            float4 v = make_float4(0.f, 0.f, 0.f, 0.f);
            if (n < n_nodes)
                v = *(const float4*)(h + (size_t)n * HF + kc * 32 + c4 * 4);
            *(float4*)&Hs[r][c4 * 4] = v;
        }
        // W chunk: Ws[k][c],  c in [0,256)
#pragma unroll
        for (int e = tid; e < 2048; e += 256) {
            int c   = e >> 3;                 // 0..255
            int k0  = (e & 7) * 4;            // 0,4,...,28
            int row = c & 127;
            int gk  = ((c >> 7) << 7) + kc * 32 + k0;
            float4 w = *(const float4*)(W1 + row * 256 + gk);
            Ws[k0 + 0][c] = w.x;
            Ws[k0 + 1][c] = w.y;
            Ws[k0 + 2][c] = w.z;
            Ws[k0 + 3][c] = w.w;
        }
        __syncthreads();

#pragma unroll
        for (int k = 0; k < 32; k++) {
            // B pairs: 4 x LDS.64, lanes cover 256B contiguous -> conflict-free
            unsigned long long b2[4];
            const unsigned long long* wrow =
                reinterpret_cast<const unsigned long long*>(&Ws[k][0]) + tx;
#pragma unroll
            for (int j = 0; j < 4; j++) b2[j] = wrow[32 * j];

            // A splats: broadcast LDS + pack {a,a}
            unsigned long long a2[8];
#pragma unroll
            for (int i = 0; i < 8; i++) {
                unsigned int ab = __float_as_uint(Hs[ty + 8 * i][k]);
                asm("mov.b64 %0, {%1, %1};" : "=l"(a2[i]) : "r"(ab));
            }
#pragma unroll
            for (int i = 0; i < 8; i++)
#pragma unroll
                for (int j = 0; j < 4; j++)
                    asm("fma.rn.f32x2 %0, %1, %2, %0;"
                        : "+l"(acc2[i][j]) : "l"(a2[i]), "l"(b2[j]));
        }
    }

    // Store: thread's col pair c = 2*tx + 64*j; j<2 -> U, j>=2 -> V
#pragma unroll
    for (int i = 0; i < 8; i++) {
        int n = n0 + ty + 8 * i;
        if (n < n_nodes) {
            float* __restrict__ urow = g_U + (size_t)n * HF;
            float* __restrict__ vrow = g_V + (size_t)n * HF;
#pragma unroll
            for (int j = 0; j < 4; j++) {
                int c = 2 * tx + 64 * j;
                unsigned int lo, hi;
                asm("mov.b64 {%0, %1}, %2;" : "=r"(lo), "=r"(hi) : "l"(acc2[i][j]));
                float2 val = make_float2(__uint_as_float(lo), __uint_as_float(hi));
                if (j < 2) *(float2*)(urow + c)        = val;
                else       *(float2*)(vrow + (c - 128)) = val;
            }
        }
    }
}

// ---------------------------------------------------------------------------
// Kernel 2: per-edge  score = W2 . relu(U[src] + V[dst] + b1) + b2
// One warp per edge, lane handles 4 consecutive features via float4.
// Index dtype (int32 vs int64) detected per-CTA from high words.
// ---------------------------------------------------------------------------
__global__ __launch_bounds__(256) void edge_score_kernel(
    const void* __restrict__ src_raw,
    const void* __restrict__ dst_raw,
    const float* __restrict__ b1,
    const float* __restrict__ W2,
    const float* __restrict__ b2,
    float* __restrict__ out,
    int n_edges,
    int n_nodes)
{
    __shared__ int s_is64;
    if (threadIdx.x == 0) {
        // If genuinely int64 (indices < 50000), every high word is 0.
        const unsigned int* p = (const unsigned int*)src_raw;
        int slots = n_edges >> 1; if (slots > 64) slots = 64;
        unsigned int acc = 0;
        for (int i = 0; i < slots; i++) acc |= p[2 * i + 1];
        s_is64 = (acc == 0u) ? 1 : 0;
    }
    __syncthreads();
    const int is64 = s_is64;

    const int lane   = threadIdx.x & 31;
    const int warp   = (blockIdx.x * blockDim.x + threadIdx.x) >> 5;
    const int nwarps = (gridDim.x * blockDim.x) >> 5;

    const float4 b14 = ((const float4*)b1)[lane];
    const float4 w24 = ((const float4*)W2)[lane];
    const float  b2v = __ldg(b2);

    const int*       src32 = (const int*)src_raw;
    const int*       dst32 = (const int*)dst_raw;
    const long long* src64 = (const long long*)src_raw;
    const long long* dst64 = (const long long*)dst_raw;

    for (int e = warp; e < n_edges; e += nwarps) {
        int s, d;
        if (is64) {
            s = (int)__ldg(src64 + e);
            d = (int)__ldg(dst64 + e);
        } else {
            s = __ldg(src32 + e);
            d = __ldg(dst32 + e);
        }
        // Safety clamp: a bad index can only give a wrong value, never a fault.
        unsigned int su = ((unsigned int)s < (unsigned int)n_nodes) ? (unsigned int)s : 0u;
        unsigned int du = ((unsigned int)d < (unsigned int)n_nodes) ? (unsigned int)d : 0u;

        float4 u = *(const float4*)(g_U + (size_t)su * HF + lane * 4);
        float4 v = *(const float4*)(g_V + (size_t)du * HF + lane * 4);

        float acc = fmaxf(u.x + v.x + b14.x, 0.f) * w24.x;
        acc = fmaf(fmaxf(u.y + v.y + b14.y, 0.f), w24.y, acc);
        acc = fmaf(fmaxf(u.z + v.z + b14.z, 0.f), w24.z, acc);
        acc = fmaf(fmaxf(u.w + v.w + b14.w, 0.f), w24.w, acc);

#pragma unroll
        for (int o = 16; o; o >>= 1)
            acc += __shfl_xor_sync(0xffffffffu, acc, o);

        if (lane == 0) out[e] = acc + b2v;
    }
}

// ---------------------------------------------------------------------------
// Launch
// ---------------------------------------------------------------------------
extern "C" void kernel_launch(void* const* d_in, const int* in_sizes, int n_in,
                              void* d_out, int out_size)
{
    const float* h   = (const float*)d_in[0];
    const void*  src = d_in[1];
    const void*  dst = d_in[2];
    const float* W1  = (const float*)d_in[3];
    const float* b1  = (const float*)d_in[4];
    const float* W2  = (const float*)d_in[5];
    const float* b2  = (const float*)d_in[6];
    float* out = (float*)d_out;

    const int n_nodes = in_sizes[0] / HF;
    const int n_edges = in_sizes[1];

    node_gemm_kernel<<<(n_nodes + 63) / 64, 256>>>(h, W1, n_nodes);
    edge_score_kernel<<<1184, 256>>>(src, dst, b1, W2, b2, out, n_edges, n_nodes);
}